// round 1
// baseline (speedup 1.0000x reference)
#include <cuda_runtime.h>
#include <math.h>

// Problem constants
#define EMBED  2048
#define LATENT 512
#define BSZ    2
#define SEQ    2048
#define NH     16
#define HD     128

// Scratch (device globals: allocation-free per harness rules)
__device__ float g_q  [(long long)BSZ * SEQ * EMBED];          // 32 MB
__device__ float g_lat[(long long)BSZ * SEQ * LATENT];         //  8 MB
__device__ float g_kv [(long long)BSZ * SEQ * 2 * EMBED];      // 64 MB
__device__ float g_sc [(long long)BSZ * NH * SEQ * SEQ];       // 512 MB
__device__ float g_att[(long long)BSZ * SEQ * EMBED];          // 32 MB

#define BM 128
#define BN 128
#define BK 16

// C[m,n] = scale * sum_k A[m,k] * B(k,n)  (+ bias[n])
// BT=true : B is (N,K) row-major  -> B(k,n) = B[n*ldb + k]   ("NT")
// BT=false: B is (K,N) row-major  -> B(k,n) = B[k*ldb + n]   ("NN")
// Batched over blockIdx.z with composite offsets: z0 = z/zdiv, z1 = z%zdiv.
template <bool BT>
__global__ __launch_bounds__(256)
void gemm_kernel(const float* __restrict__ A, const float* __restrict__ B,
                 const float* __restrict__ bias, float* __restrict__ C,
                 int M, int N, int K, int lda, int ldb, int ldc, float scale,
                 int zdiv,
                 long long sA0, long long sA1,
                 long long sB0, long long sB1,
                 long long sC0, long long sC1)
{
    const int z  = blockIdx.z;
    const int z0 = z / zdiv;
    const int z1 = z % zdiv;
    A += z0 * sA0 + z1 * sA1;
    B += z0 * sB0 + z1 * sB1;
    C += z0 * sC0 + z1 * sC1;

    __shared__ float As[BK][BM];
    __shared__ float Bs[BK][BN];

    const int tid = threadIdx.x;
    const int bm  = blockIdx.y * BM;
    const int bn  = blockIdx.x * BN;

    const int ty = tid >> 4;    // 0..15
    const int tx = tid & 15;    // 0..15

    // transpose-load mapping (A and NT-B): 128 rows x 16 k, 2 float4 per thread
    const int trow = tid >> 1;          // 0..127
    const int tkq  = (tid & 1) * 8;     // 0 or 8

    float acc[8][8];
#pragma unroll
    for (int i = 0; i < 8; i++)
#pragma unroll
        for (int j = 0; j < 8; j++) acc[i][j] = 0.f;

    for (int kk = 0; kk < K; kk += BK) {
        // ---- load A tile (transposed into shared) ----
        {
            const float4* ap = reinterpret_cast<const float4*>(
                A + (long long)(bm + trow) * lda + kk + tkq);
            float4 a0 = ap[0];
            float4 a1 = ap[1];
            As[tkq + 0][trow] = a0.x; As[tkq + 1][trow] = a0.y;
            As[tkq + 2][trow] = a0.z; As[tkq + 3][trow] = a0.w;
            As[tkq + 4][trow] = a1.x; As[tkq + 5][trow] = a1.y;
            As[tkq + 6][trow] = a1.z; As[tkq + 7][trow] = a1.w;
        }
        // ---- load B tile ----
        if (BT) {
            const float4* bp = reinterpret_cast<const float4*>(
                B + (long long)(bn + trow) * ldb + kk + tkq);
            float4 b0 = bp[0];
            float4 b1 = bp[1];
            Bs[tkq + 0][trow] = b0.x; Bs[tkq + 1][trow] = b0.y;
            Bs[tkq + 2][trow] = b0.z; Bs[tkq + 3][trow] = b0.w;
            Bs[tkq + 4][trow] = b1.x; Bs[tkq + 5][trow] = b1.y;
            Bs[tkq + 6][trow] = b1.z; Bs[tkq + 7][trow] = b1.w;
        } else {
            const int bk0 = tid >> 5;          // 0..7
            const int bn4 = (tid & 31) * 4;    // 0..124
            float4 v0 = *reinterpret_cast<const float4*>(
                B + (long long)(kk + bk0) * ldb + bn + bn4);
            float4 v1 = *reinterpret_cast<const float4*>(
                B + (long long)(kk + bk0 + 8) * ldb + bn + bn4);
            *reinterpret_cast<float4*>(&Bs[bk0][bn4])     = v0;
            *reinterpret_cast<float4*>(&Bs[bk0 + 8][bn4]) = v1;
        }
        __syncthreads();

#pragma unroll
        for (int k = 0; k < BK; k++) {
            float a[8], b[8];
            *reinterpret_cast<float4*>(a)     = *reinterpret_cast<const float4*>(&As[k][ty * 8]);
            *reinterpret_cast<float4*>(a + 4) = *reinterpret_cast<const float4*>(&As[k][ty * 8 + 4]);
            *reinterpret_cast<float4*>(b)     = *reinterpret_cast<const float4*>(&Bs[k][tx * 8]);
            *reinterpret_cast<float4*>(b + 4) = *reinterpret_cast<const float4*>(&Bs[k][tx * 8 + 4]);
#pragma unroll
            for (int i = 0; i < 8; i++)
#pragma unroll
                for (int j = 0; j < 8; j++)
                    acc[i][j] = fmaf(a[i], b[j], acc[i][j]);
        }
        __syncthreads();
    }

    // ---- epilogue: scale + bias + store ----
    float bv[8];
#pragma unroll
    for (int j = 0; j < 8; j++)
        bv[j] = bias ? bias[bn + tx * 8 + j] : 0.f;

#pragma unroll
    for (int i = 0; i < 8; i++) {
        const long long m = bm + ty * 8 + i;
        float o[8];
#pragma unroll
        for (int j = 0; j < 8; j++) o[j] = acc[i][j] * scale + bv[j];
        float* cp = C + m * ldc + bn + tx * 8;
        *reinterpret_cast<float4*>(cp)     = *reinterpret_cast<float4*>(o);
        *reinterpret_cast<float4*>(cp + 4) = *reinterpret_cast<float4*>(o + 4);
    }
}

// Row softmax, one block (256 threads) per row of `cols` floats.
__global__ __launch_bounds__(256)
void softmax_kernel(float* __restrict__ S, int cols)
{
    const long long row = blockIdx.x;
    float* p = S + row * (long long)cols;
    const int tid = threadIdx.x;
    __shared__ float red[256];

    // pass 1: max
    float m = -1e30f;
    for (int i = tid * 4; i < cols; i += 256 * 4) {
        float4 v = *reinterpret_cast<const float4*>(p + i);
        m = fmaxf(m, fmaxf(fmaxf(v.x, v.y), fmaxf(v.z, v.w)));
    }
    red[tid] = m;
    __syncthreads();
    for (int s = 128; s > 0; s >>= 1) {
        if (tid < s) red[tid] = fmaxf(red[tid], red[tid + s]);
        __syncthreads();
    }
    m = red[0];
    __syncthreads();

    // pass 2: exp + sum
    float sum = 0.f;
    for (int i = tid * 4; i < cols; i += 256 * 4) {
        float4 v = *reinterpret_cast<const float4*>(p + i);
        v.x = __expf(v.x - m); v.y = __expf(v.y - m);
        v.z = __expf(v.z - m); v.w = __expf(v.w - m);
        sum += v.x + v.y + v.z + v.w;
        *reinterpret_cast<float4*>(p + i) = v;
    }
    red[tid] = sum;
    __syncthreads();
    for (int s = 128; s > 0; s >>= 1) {
        if (tid < s) red[tid] += red[tid + s];
        __syncthreads();
    }
    const float inv = 1.f / red[0];

    // pass 3: normalize
    for (int i = tid * 4; i < cols; i += 256 * 4) {
        float4 v = *reinterpret_cast<const float4*>(p + i);
        v.x *= inv; v.y *= inv; v.z *= inv; v.w *= inv;
        *reinterpret_cast<float4*>(p + i) = v;
    }
}

extern "C" void kernel_launch(void* const* d_in, const int* in_sizes, int n_in,
                              void* d_out, int out_size)
{
    const float* x     = (const float*)d_in[0];
    const float* q_w   = (const float*)d_in[1];
    const float* q_b   = (const float*)d_in[2];
    const float* kvd_w = (const float*)d_in[3];
    const float* kvd_b = (const float*)d_in[4];
    const float* kvu_w = (const float*)d_in[5];
    const float* kvu_b = (const float*)d_in[6];
    const float* out_w = (const float*)d_in[7];
    const float* out_b = (const float*)d_in[8];
    float* out = (float*)d_out;

    float *q, *lat, *kv, *sc, *att;
    cudaGetSymbolAddress((void**)&q,   g_q);
    cudaGetSymbolAddress((void**)&lat, g_lat);
    cudaGetSymbolAddress((void**)&kv,  g_kv);
    cudaGetSymbolAddress((void**)&sc,  g_sc);
    cudaGetSymbolAddress((void**)&att, g_att);

    const int M = BSZ * SEQ;  // 4096 rows
    const dim3 blk(256);

    // 1) q = x @ q_w^T + q_b                     [4096, 2048]
    gemm_kernel<true><<<dim3(EMBED / BN, M / BM, 1), blk>>>(
        x, q_w, q_b, q, M, EMBED, EMBED, EMBED, EMBED, EMBED, 1.f,
        1, 0, 0, 0, 0, 0, 0);

    // 2) latent = x @ kvd_w^T + kvd_b            [4096, 512]
    gemm_kernel<true><<<dim3(LATENT / BN, M / BM, 1), blk>>>(
        x, kvd_w, kvd_b, lat, M, LATENT, EMBED, EMBED, EMBED, LATENT, 1.f,
        1, 0, 0, 0, 0, 0, 0);

    // 3) kv = latent @ kvu_w^T + kvu_b           [4096, 4096]
    gemm_kernel<true><<<dim3(2 * EMBED / BN, M / BM, 1), blk>>>(
        lat, kvu_w, kvu_b, kv, M, 2 * EMBED, LATENT, LATENT, LATENT, 2 * EMBED, 1.f,
        1, 0, 0, 0, 0, 0, 0);

    // 4) scores[z] = (q_h @ k_h^T) / sqrt(D), z = b*NH + h  -> 32 batches
    const long long sQb  = (long long)SEQ * EMBED;
    const long long sKVb = (long long)SEQ * 2 * EMBED;
    const long long sSz  = (long long)SEQ * SEQ;
    const float iscale = 1.0f / sqrtf((float)HD);
    gemm_kernel<true><<<dim3(SEQ / BN, SEQ / BM, BSZ * NH), blk>>>(
        q, kv, nullptr, sc,
        SEQ, SEQ, HD, EMBED, 2 * EMBED, SEQ, iscale,
        NH, sQb, (long long)HD, sKVb, (long long)HD, sSz * NH, sSz);

    // 5) softmax over last dim of scores (65536 rows of 2048)
    softmax_kernel<<<BSZ * NH * SEQ, 256>>>(sc, SEQ);

    // 6) att[z] = attn @ v_h                     [2048, 128] per (b,h)
    gemm_kernel<false><<<dim3(HD / BN, SEQ / BM, BSZ * NH), blk>>>(
        sc, kv + EMBED, nullptr, att,
        SEQ, HD, SEQ, SEQ, 2 * EMBED, EMBED, 1.f,
        NH, sSz * NH, sSz, sKVb, (long long)HD, sQb, (long long)HD);

    // 7) out = att @ out_w^T + out_b             [4096, 2048]
    gemm_kernel<true><<<dim3(EMBED / BN, M / BM, 1), blk>>>(
        att, out_w, out_b, out, M, EMBED, EMBED, EMBED, EMBED, EMBED, 1.f,
        1, 0, 0, 0, 0, 0, 0);
}

// round 3
// speedup vs baseline: 2.8971x; 2.8971x over previous
#include <cuda_runtime.h>
#include <cuda_bf16.h>
#include <math.h>
#include <stdint.h>

#define EMBED  2048
#define LATENT 512
#define BSZ    2
#define SEQ    2048
#define NH     16
#define HD     128

typedef __nv_bfloat16 bf16;

// Does this compilation pass have tcgen05 (arch-specific sm_103a/sm_100a)?
#if !defined(__CUDA_ARCH__) || defined(__CUDA_ARCH_FEAT_SM103_ALL) || \
    defined(__CUDA_ARCH_FEAT_SM100_ALL) || defined(__CUDA_ARCH_SPECIFIC__) || \
    defined(__CUDA_ARCH_FAMILY_SPECIFIC__)
#define USE_TC 1
#else
#define USE_TC 0
#endif

// ---------------- device scratch (allocation-free) ----------------
#define XN   (2LL*2048*2048)
#define LATN (2LL*2048*512)
#define KVN  (2LL*2048*4096)
#define SCN  (2LL*16*2048*2048)

__device__ bf16  g_x_hi[XN],    g_x_lo[XN];
__device__ bf16  g_qw_hi[EMBED*EMBED],   g_qw_lo[EMBED*EMBED];
__device__ bf16  g_kvdw_hi[LATENT*EMBED], g_kvdw_lo[LATENT*EMBED];
__device__ bf16  g_kvuw_hi[2*EMBED*LATENT], g_kvuw_lo[2*EMBED*LATENT];
__device__ bf16  g_ow_hi[EMBED*EMBED],   g_ow_lo[EMBED*EMBED];
__device__ bf16  g_q_hi[XN],    g_q_lo[XN];
__device__ bf16  g_lat_hi[LATN], g_lat_lo[LATN];
__device__ float g_kv[KVN];
__device__ bf16  g_k_hi[XN],    g_k_lo[XN];
__device__ bf16  g_vt_hi[XN],   g_vt_lo[XN];
__device__ float g_sc[SCN];
__device__ bf16  g_p_hi[SCN],   g_p_lo[SCN];
__device__ bf16  g_att_hi[XN],  g_att_lo[XN];

// ---------------- common helpers ----------------
__device__ __forceinline__ uint32_t smem_u32(const void* p) {
    uint32_t a;
    asm("{ .reg .u64 t; cvta.to.shared.u64 t, %1; cvt.u32.u64 %0, t; }"
        : "=r"(a) : "l"(p));
    return a;
}
#define SWZ(x) ((x) ^ (((x) >> 3) & 0x70))

__device__ __forceinline__ void split2(float v, bf16& h, bf16& l) {
    h = __float2bfloat16(v);
    l = __float2bfloat16(v - __bfloat162float(h));
}

#if USE_TC
// ---------------- tcgen05 helpers (arch-specific pass only) ----------------
__device__ __forceinline__ uint32_t elect1() {
    uint32_t p;
    asm volatile("{ .reg .pred p; elect.sync _|p, 0xFFFFFFFF; selp.b32 %0,1,0,p; }"
                 : "=r"(p));
    return p;
}
#define TC_ALLOC(sa, n) \
    asm volatile("tcgen05.alloc.cta_group::1.sync.aligned.shared::cta.b32 [%0], %1;" \
                 :: "r"(sa), "r"(n) : "memory")
#define TC_DEALLOC(t, n) \
    asm volatile("tcgen05.dealloc.cta_group::1.sync.aligned.b32 %0, %1;" :: "r"(t), "r"(n))
#define TC_COMMIT(mb) \
    asm volatile("tcgen05.commit.cta_group::1.mbarrier::arrive::one.shared::cluster.b64 [%0];" \
                 :: "r"(mb) : "memory")
#define TC_FENCE_AFTER()  asm volatile("tcgen05.fence::after_thread_sync;" ::: "memory")
#define TC_WAIT_LD()      asm volatile("tcgen05.wait::ld.sync.aligned;" ::: "memory")
#define MBAR_INIT(mb, c) \
    asm volatile("mbarrier.init.shared.b64 [%0], %1;" :: "r"(mb), "r"(c) : "memory")
#define MBAR_WAIT(mb, ph) do { \
    uint32_t _mb = (mb); uint32_t _ph = (ph); uint32_t _done; \
    asm volatile("{ .reg .pred p; mbarrier.try_wait.parity.acquire.cta.shared::cta.b64 p, [%1], %2; selp.b32 %0,1,0,p; }" \
        : "=r"(_done) : "r"(_mb), "r"(_ph) : "memory"); \
    if (!_done) { \
        asm volatile("{ .reg .pred P1; WL_%=: mbarrier.try_wait.parity.acquire.cta.shared::cta.b64 P1, [%0], %1, 0x989680; @P1 bra.uni WD_%=; bra.uni WL_%=; WD_%=: }" \
            :: "r"(_mb), "r"(_ph) : "memory"); \
    } } while (0)

__device__ __forceinline__ void mma_bf16_ss(uint32_t d, uint64_t a, uint64_t b,
                                            uint32_t idesc, uint32_t en) {
    asm volatile(
        "{ .reg .pred p; setp.ne.u32 p, %5, 0;\n\t"
        "tcgen05.mma.cta_group::1.kind::f16 [%0], %1, %2, %3, {%4,%4,%4,%4}, p; }"
        :: "r"(d), "l"(a), "l"(b), "r"(idesc), "r"(0u), "r"(en) : "memory");
}
__device__ __forceinline__ void tmem_ld32(uint32_t* r, uint32_t a) {
    asm volatile(
        "tcgen05.ld.sync.aligned.32x32b.x32.b32 "
        "{%0,%1,%2,%3,%4,%5,%6,%7,%8,%9,%10,%11,%12,%13,%14,%15,"
        "%16,%17,%18,%19,%20,%21,%22,%23,%24,%25,%26,%27,%28,%29,%30,%31}, [%32];"
        : "=r"(r[0]), "=r"(r[1]), "=r"(r[2]), "=r"(r[3]), "=r"(r[4]), "=r"(r[5]),
          "=r"(r[6]), "=r"(r[7]), "=r"(r[8]), "=r"(r[9]), "=r"(r[10]), "=r"(r[11]),
          "=r"(r[12]), "=r"(r[13]), "=r"(r[14]), "=r"(r[15]), "=r"(r[16]), "=r"(r[17]),
          "=r"(r[18]), "=r"(r[19]), "=r"(r[20]), "=r"(r[21]), "=r"(r[22]), "=r"(r[23]),
          "=r"(r[24]), "=r"(r[25]), "=r"(r[26]), "=r"(r[27]), "=r"(r[28]), "=r"(r[29]),
          "=r"(r[30]), "=r"(r[31])
        : "r"(a));
}
__device__ __forceinline__ uint64_t mkdesc(uint32_t addr) {
    const uint64_t base = (2ULL << 61) | (1ULL << 46) | (64ULL << 32) | (1ULL << 16);
    return base | ((uint64_t)(addr >> 4) & 0x3FFF);
}
// idesc: F32 acc, BF16 a/b, K-major both, M=128, N=128
#define IDESC 0x8200490u
#else
// ---------------- generic-pass helpers: mma.sync + cp.async ----------------
__device__ __forceinline__ void cpasync16(uint32_t dst, const void* src) {
    asm volatile("cp.async.cg.shared.global [%0], [%1], 16;"
                 :: "r"(dst), "l"(src) : "memory");
}
__device__ __forceinline__ void ldsm_x4(uint32_t* r, uint32_t addr) {
    asm volatile("ldmatrix.sync.aligned.m8n8.x4.shared.b16 {%0,%1,%2,%3}, [%4];"
                 : "=r"(r[0]), "=r"(r[1]), "=r"(r[2]), "=r"(r[3]) : "r"(addr));
}
__device__ __forceinline__ void ldsm_x2(uint32_t* r, uint32_t addr) {
    asm volatile("ldmatrix.sync.aligned.m8n8.x2.shared.b16 {%0,%1}, [%2];"
                 : "=r"(r[0]), "=r"(r[1]) : "r"(addr));
}
__device__ __forceinline__ void mma16816(float* d, const uint32_t* a, const uint32_t* b) {
    asm volatile(
        "mma.sync.aligned.m16n8k16.row.col.f32.bf16.bf16.f32 "
        "{%0,%1,%2,%3}, {%4,%5,%6,%7}, {%8,%9}, {%0,%1,%2,%3};"
        : "+f"(d[0]), "+f"(d[1]), "+f"(d[2]), "+f"(d[3])
        : "r"(a[0]), "r"(a[1]), "r"(a[2]), "r"(a[3]), "r"(b[0]), "r"(b[1]));
}
#endif

// ---------------- split-bf16 GEMM (128x128 tile), dual backend ----------------
// C[m,n] = scale * sum_k A(m,k)B(n,k) + bias[n]; A,B = (hi,lo) bf16 planes,
// K-major rows, K % 64 == 0. OUTM=0: fp32 C. OUTM=1: (hi,lo) bf16 outputs.
#define SMEM_TILES 1024
#define SMEM_BYTES (1024 + 2 * 65536)

template <int OUTM>
__global__ __launch_bounds__(256)
void tgemm(const bf16* __restrict__ Ahi, const bf16* __restrict__ Alo, int lda,
           const bf16* __restrict__ Bhi, const bf16* __restrict__ Blo, int ldb,
           const float* __restrict__ bias, float scale,
           float* __restrict__ Cf, bf16* __restrict__ Chi, bf16* __restrict__ Clo,
           int ldc, int K, int zdiv,
           long long sA0, long long sA1, long long sB0, long long sB1,
           long long sC0, long long sC1)
{
    extern __shared__ char smem[];
    const int tid = threadIdx.x;
    const int wid = tid >> 5, lid = tid & 31;
    const uint32_t sb = smem_u32(smem);

    const int z = blockIdx.z, z0 = z / zdiv, z1 = z % zdiv;
    const long long aoff = z0 * sA0 + z1 * sA1;
    const long long boff = z0 * sB0 + z1 * sB1;
    const long long coff = z0 * sC0 + z1 * sC1;

    const int bm = blockIdx.y * 128, bn = blockIdx.x * 128;

    // loader mapping: thread owns 16B segment `seg` of rows r0+32i
    const int seg = tid & 7;
    const int r0  = tid >> 3;
    const bf16* pAh = Ahi + aoff + (long long)(bm + r0) * lda + seg * 8;
    const bf16* pAl = Alo + aoff + (long long)(bm + r0) * lda + seg * 8;
    const bf16* pBh = Bhi + boff + (long long)(bn + r0) * ldb + seg * 8;
    const bf16* pBl = Blo + boff + (long long)(bn + r0) * ldb + seg * 8;

    const int KC = K >> 6;

#if USE_TC
    if (wid == 0) TC_ALLOC(sb, 128);
    if (tid == 0) { MBAR_INIT(sb + 8, 1); MBAR_INIT(sb + 16, 1); }
    __syncthreads();
    uint32_t tmem;
    asm volatile("ld.shared.b32 %0, [%1];" : "=r"(tmem) : "r"(sb));

    const uint32_t mb[2] = { sb + 8, sb + 16 };

    for (int kc = 0; kc < KC; kc++) {
        const int buf = kc & 1;
        const int kk = kc << 6;

        uint4 va[4], vb[4], vc[4], vd[4];
#pragma unroll
        for (int i = 0; i < 4; i++) {
            const long long ra = (long long)(i * 32) * lda + kk;
            const long long rb = (long long)(i * 32) * ldb + kk;
            va[i] = *reinterpret_cast<const uint4*>(pAh + ra);
            vb[i] = *reinterpret_cast<const uint4*>(pAl + ra);
            vc[i] = *reinterpret_cast<const uint4*>(pBh + rb);
            vd[i] = *reinterpret_cast<const uint4*>(pBl + rb);
        }

        const int u = kc >> 1;
        if (u >= 1) MBAR_WAIT(mb[buf], (u - 1) & 1);

        char* tb = smem + SMEM_TILES + buf * 65536;
#pragma unroll
        for (int i = 0; i < 4; i++) {
            const uint32_t sw = SWZ(((r0 + i * 32) << 7) + (seg << 4));
            *reinterpret_cast<uint4*>(tb + sw)         = va[i];
            *reinterpret_cast<uint4*>(tb + 16384 + sw) = vb[i];
            *reinterpret_cast<uint4*>(tb + 32768 + sw) = vc[i];
            *reinterpret_cast<uint4*>(tb + 49152 + sw) = vd[i];
        }
        asm volatile("fence.proxy.async.shared::cta;" ::: "memory");
        __syncthreads();

        if (wid == 0) {
            if (elect1()) {
                const uint32_t tbu = sb + SMEM_TILES + buf * 65536;
                const uint64_t dah = mkdesc(tbu);
                const uint64_t dal = mkdesc(tbu + 16384);
                const uint64_t dbh = mkdesc(tbu + 32768);
                const uint64_t dbl = mkdesc(tbu + 49152);
#pragma unroll
                for (int t = 0; t < 3; t++) {
                    const uint64_t da = (t == 2) ? dal : dah;
                    const uint64_t db = (t == 1) ? dbl : dbh;
#pragma unroll
                    for (int ks = 0; ks < 4; ks++) {
                        const uint32_t en = !(kc == 0 && t == 0 && ks == 0);
                        mma_bf16_ss(tmem, da + ks * 2, db + ks * 2, IDESC, en);
                    }
                }
                TC_COMMIT(mb[buf]);
            }
        }
    }

    MBAR_WAIT(mb[(KC - 1) & 1], ((KC - 1) >> 1) & 1);
    TC_FENCE_AFTER();

    if (tid < 128) {
        const long long m = bm + wid * 32 + lid;
#pragma unroll 1
        for (int cb = 0; cb < 4; cb++) {
            uint32_t r[32];
            tmem_ld32(r, tmem + cb * 32);
            TC_WAIT_LD();
            const int n0 = bn + cb * 32;
            if (OUTM == 0) {
                alignas(16) float o[32];
#pragma unroll
                for (int c = 0; c < 32; c++) {
                    float v = __uint_as_float(r[c]) * scale;
                    if (bias) v += bias[n0 + c];
                    o[c] = v;
                }
                float* cp = Cf + coff + m * ldc + n0;
#pragma unroll
                for (int q4 = 0; q4 < 8; q4++)
                    *reinterpret_cast<float4*>(cp + q4 * 4) =
                        *reinterpret_cast<const float4*>(o + q4 * 4);
            } else {
                alignas(16) bf16 hv[32], lv[32];
#pragma unroll
                for (int c = 0; c < 32; c++) {
                    float v = __uint_as_float(r[c]) * scale;
                    if (bias) v += bias[n0 + c];
                    split2(v, hv[c], lv[c]);
                }
                bf16* hp = Chi + coff + m * ldc + n0;
                bf16* lp = Clo + coff + m * ldc + n0;
#pragma unroll
                for (int q4 = 0; q4 < 4; q4++) {
                    *reinterpret_cast<uint4*>(hp + q4 * 8) =
                        *reinterpret_cast<const uint4*>(hv + q4 * 8);
                    *reinterpret_cast<uint4*>(lp + q4 * 8) =
                        *reinterpret_cast<const uint4*>(lv + q4 * 8);
                }
            }
        }
    }
    __syncthreads();
    if (wid == 0) TC_DEALLOC(tmem, 128);

#else  // ================= generic mma.sync fallback =================
    const int wm = (wid & 1) * 64;   // 2 M warp-tiles of 64
    const int wn = (wid >> 1) * 32;  // 4 N warp-tiles of 32

    float acc[4][4][4];
#pragma unroll
    for (int mi = 0; mi < 4; mi++)
#pragma unroll
        for (int ni = 0; ni < 4; ni++)
#pragma unroll
            for (int c = 0; c < 4; c++) acc[mi][ni][c] = 0.f;

    auto issue_chunk = [&](int kc) {
        const int buf = kc & 1;
        const int kk = kc << 6;
        const uint32_t tb = sb + SMEM_TILES + buf * 65536;
#pragma unroll
        for (int i = 0; i < 4; i++) {
            const uint32_t sw = SWZ(((r0 + i * 32) << 7) + (seg << 4));
            const long long ra = (long long)(i * 32) * lda + kk;
            const long long rb = (long long)(i * 32) * ldb + kk;
            cpasync16(tb + sw,         pAh + ra);
            cpasync16(tb + 16384 + sw, pAl + ra);
            cpasync16(tb + 32768 + sw, pBh + rb);
            cpasync16(tb + 49152 + sw, pBl + rb);
        }
        asm volatile("cp.async.commit_group;" ::: "memory");
    };

    issue_chunk(0);

    const int arow  = wm + (lid & 15);
    const uint32_t akb = (lid >> 4) * 16;        // 0 or 16
    const int brow  = wn + (lid & 7);
    const uint32_t bkb = ((lid >> 3) & 1) * 16;  // 0 or 16 (lanes >=16 unused)

    for (int kc = 0; kc < KC; kc++) {
        if (kc + 1 < KC) {
            issue_chunk(kc + 1);
            asm volatile("cp.async.wait_group 1;" ::: "memory");
        } else {
            asm volatile("cp.async.wait_group 0;" ::: "memory");
        }
        __syncthreads();

        const uint32_t tb = sb + SMEM_TILES + (kc & 1) * 65536;
#pragma unroll
        for (int ks = 0; ks < 4; ks++) {
            uint32_t ah[4][4], al[4][4], bh[4][2], bl[4][2];
#pragma unroll
            for (int mi = 0; mi < 4; mi++) {
                const uint32_t off = SWZ((uint32_t)((arow + mi * 16) << 7) + ks * 32 + akb);
                ldsm_x4(ah[mi], tb + off);
                ldsm_x4(al[mi], tb + 16384 + off);
            }
#pragma unroll
            for (int ni = 0; ni < 4; ni++) {
                const uint32_t off = SWZ((uint32_t)((brow + ni * 8) << 7) + ks * 32 + bkb);
                ldsm_x2(bh[ni], tb + 32768 + off);
                ldsm_x2(bl[ni], tb + 49152 + off);
            }
#pragma unroll
            for (int mi = 0; mi < 4; mi++)
#pragma unroll
                for (int ni = 0; ni < 4; ni++) {
                    mma16816(acc[mi][ni], ah[mi], bh[ni]);
                    mma16816(acc[mi][ni], ah[mi], bl[ni]);
                    mma16816(acc[mi][ni], al[mi], bh[ni]);
                }
        }
        __syncthreads();
    }

    // epilogue: m16n8 acc layout — lane l: rows l/4 and l/4+8, cols (l%4)*2, +1
    const int lr  = lid >> 2;
    const int lc2 = (lid & 3) * 2;
#pragma unroll
    for (int mi = 0; mi < 4; mi++) {
        const long long m0 = bm + wm + mi * 16 + lr;
#pragma unroll
        for (int ni = 0; ni < 4; ni++) {
            const int col = bn + wn + ni * 8 + lc2;
            const float b0 = bias ? bias[col] : 0.f;
            const float b1 = bias ? bias[col + 1] : 0.f;
            const float v00 = acc[mi][ni][0] * scale + b0;
            const float v01 = acc[mi][ni][1] * scale + b1;
            const float v10 = acc[mi][ni][2] * scale + b0;
            const float v11 = acc[mi][ni][3] * scale + b1;
            if (OUTM == 0) {
                *reinterpret_cast<float2*>(Cf + coff + m0 * ldc + col) =
                    make_float2(v00, v01);
                *reinterpret_cast<float2*>(Cf + coff + (m0 + 8) * ldc + col) =
                    make_float2(v10, v11);
            } else {
                bf16 h0, l0, h1, l1;
                split2(v00, h0, l0); split2(v01, h1, l1);
                alignas(4) bf16 hp0[2] = {h0, h1}, lp0[2] = {l0, l1};
                *reinterpret_cast<uint32_t*>(Chi + coff + m0 * ldc + col) =
                    *reinterpret_cast<uint32_t*>(hp0);
                *reinterpret_cast<uint32_t*>(Clo + coff + m0 * ldc + col) =
                    *reinterpret_cast<uint32_t*>(lp0);
                split2(v10, h0, l0); split2(v11, h1, l1);
                alignas(4) bf16 hp1[2] = {h0, h1}, lp1[2] = {l0, l1};
                *reinterpret_cast<uint32_t*>(Chi + coff + (m0 + 8) * ldc + col) =
                    *reinterpret_cast<uint32_t*>(hp1);
                *reinterpret_cast<uint32_t*>(Clo + coff + (m0 + 8) * ldc + col) =
                    *reinterpret_cast<uint32_t*>(lp1);
            }
        }
    }
#endif
}

// ---------------- elementwise split kernels ----------------
__global__ void split_kernel(const float* __restrict__ in,
                             bf16* __restrict__ hi, bf16* __restrict__ lo,
                             long long n)
{
    const long long i = ((long long)blockIdx.x * blockDim.x + threadIdx.x) * 4;
    if (i >= n) return;
    const float4 v = *reinterpret_cast<const float4*>(in + i);
    alignas(8) bf16 h[4], l[4];
    split2(v.x, h[0], l[0]); split2(v.y, h[1], l[1]);
    split2(v.z, h[2], l[2]); split2(v.w, h[3], l[3]);
    *reinterpret_cast<uint2*>(hi + i) = *reinterpret_cast<const uint2*>(h);
    *reinterpret_cast<uint2*>(lo + i) = *reinterpret_cast<const uint2*>(l);
}

__global__ void ksplit_kernel(const float* __restrict__ kv,
                              bf16* __restrict__ khi, bf16* __restrict__ klo)
{
    const long long i = ((long long)blockIdx.x * blockDim.x + threadIdx.x) * 4;
    if (i >= XN) return;
    const long long row = i >> 11, col = i & 2047;
    const float4 v = *reinterpret_cast<const float4*>(kv + row * 4096 + col);
    alignas(8) bf16 h[4], l[4];
    split2(v.x, h[0], l[0]); split2(v.y, h[1], l[1]);
    split2(v.z, h[2], l[2]); split2(v.w, h[3], l[3]);
    *reinterpret_cast<uint2*>(khi + i) = *reinterpret_cast<const uint2*>(h);
    *reinterpret_cast<uint2*>(klo + i) = *reinterpret_cast<const uint2*>(l);
}

__global__ void vtrans_kernel(const float* __restrict__ kv,
                              bf16* __restrict__ vthi, bf16* __restrict__ vtlo)
{
    __shared__ float t[32][33];
    const int b = blockIdx.z >> 4, h = blockIdx.z & 15;
    const int s0 = blockIdx.x * 32, d0 = blockIdx.y * 32;
    const int tx = threadIdx.x, ty = threadIdx.y;
    t[ty][tx] = kv[(long long)(b * SEQ + s0 + ty) * 4096 + 2048 + h * 128 + d0 + tx];
    __syncthreads();
    const float v = t[tx][ty];
    const long long o = (long long)((b * NH + h) * HD + d0 + ty) * SEQ + s0 + tx;
    bf16 hv, lv;
    split2(v, hv, lv);
    vthi[o] = hv;
    vtlo[o] = lv;
}

// ---------------- softmax: fp32 scores -> (hi,lo) bf16 P ----------------
__global__ __launch_bounds__(256)
void softmax_split(float* __restrict__ S, bf16* __restrict__ Phi,
                   bf16* __restrict__ Plo, int cols)
{
    const long long row = blockIdx.x;
    float* p = S + row * (long long)cols;
    bf16* ph = Phi + row * (long long)cols;
    bf16* pl = Plo + row * (long long)cols;
    const int tid = threadIdx.x;
    __shared__ float red[256];

    float m = -1e30f;
    for (int i = tid * 4; i < cols; i += 1024) {
        float4 v = *reinterpret_cast<const float4*>(p + i);
        m = fmaxf(m, fmaxf(fmaxf(v.x, v.y), fmaxf(v.z, v.w)));
    }
    red[tid] = m;
    __syncthreads();
    for (int s = 128; s > 0; s >>= 1) {
        if (tid < s) red[tid] = fmaxf(red[tid], red[tid + s]);
        __syncthreads();
    }
    m = red[0];
    __syncthreads();

    float sum = 0.f;
    for (int i = tid * 4; i < cols; i += 1024) {
        float4 v = *reinterpret_cast<const float4*>(p + i);
        v.x = __expf(v.x - m); v.y = __expf(v.y - m);
        v.z = __expf(v.z - m); v.w = __expf(v.w - m);
        sum += v.x + v.y + v.z + v.w;
        *reinterpret_cast<float4*>(p + i) = v;
    }
    red[tid] = sum;
    __syncthreads();
    for (int s = 128; s > 0; s >>= 1) {
        if (tid < s) red[tid] += red[tid + s];
        __syncthreads();
    }
    const float inv = 1.f / red[0];

    for (int i = tid * 4; i < cols; i += 1024) {
        float4 v = *reinterpret_cast<const float4*>(p + i);
        alignas(8) bf16 h[4], l[4];
        split2(v.x * inv, h[0], l[0]); split2(v.y * inv, h[1], l[1]);
        split2(v.z * inv, h[2], l[2]); split2(v.w * inv, h[3], l[3]);
        *reinterpret_cast<uint2*>(ph + i) = *reinterpret_cast<const uint2*>(h);
        *reinterpret_cast<uint2*>(pl + i) = *reinterpret_cast<const uint2*>(l);
    }
}

// ---------------- host ----------------
static void do_split(const float* in, bf16* hi, bf16* lo, long long n) {
    split_kernel<<<(unsigned)((n / 4 + 255) / 256), 256>>>(in, hi, lo, n);
}

extern "C" void kernel_launch(void* const* d_in, const int* in_sizes, int n_in,
                              void* d_out, int out_size)
{
    const float* x     = (const float*)d_in[0];
    const float* q_w   = (const float*)d_in[1];
    const float* q_b   = (const float*)d_in[2];
    const float* kvd_w = (const float*)d_in[3];
    const float* kvd_b = (const float*)d_in[4];
    const float* kvu_w = (const float*)d_in[5];
    const float* kvu_b = (const float*)d_in[6];
    const float* out_w = (const float*)d_in[7];
    const float* out_b = (const float*)d_in[8];
    float* out = (float*)d_out;

    bf16 *x_hi, *x_lo, *qw_hi, *qw_lo, *kvdw_hi, *kvdw_lo, *kvuw_hi, *kvuw_lo,
         *ow_hi, *ow_lo, *q_hi, *q_lo, *lat_hi, *lat_lo, *k_hi, *k_lo,
         *vt_hi, *vt_lo, *p_hi, *p_lo, *att_hi, *att_lo;
    float *kv, *sc;
    cudaGetSymbolAddress((void**)&x_hi, g_x_hi);     cudaGetSymbolAddress((void**)&x_lo, g_x_lo);
    cudaGetSymbolAddress((void**)&qw_hi, g_qw_hi);   cudaGetSymbolAddress((void**)&qw_lo, g_qw_lo);
    cudaGetSymbolAddress((void**)&kvdw_hi, g_kvdw_hi); cudaGetSymbolAddress((void**)&kvdw_lo, g_kvdw_lo);
    cudaGetSymbolAddress((void**)&kvuw_hi, g_kvuw_hi); cudaGetSymbolAddress((void**)&kvuw_lo, g_kvuw_lo);
    cudaGetSymbolAddress((void**)&ow_hi, g_ow_hi);   cudaGetSymbolAddress((void**)&ow_lo, g_ow_lo);
    cudaGetSymbolAddress((void**)&q_hi, g_q_hi);     cudaGetSymbolAddress((void**)&q_lo, g_q_lo);
    cudaGetSymbolAddress((void**)&lat_hi, g_lat_hi); cudaGetSymbolAddress((void**)&lat_lo, g_lat_lo);
    cudaGetSymbolAddress((void**)&k_hi, g_k_hi);     cudaGetSymbolAddress((void**)&k_lo, g_k_lo);
    cudaGetSymbolAddress((void**)&vt_hi, g_vt_hi);   cudaGetSymbolAddress((void**)&vt_lo, g_vt_lo);
    cudaGetSymbolAddress((void**)&p_hi, g_p_hi);     cudaGetSymbolAddress((void**)&p_lo, g_p_lo);
    cudaGetSymbolAddress((void**)&att_hi, g_att_hi); cudaGetSymbolAddress((void**)&att_lo, g_att_lo);
    cudaGetSymbolAddress((void**)&kv, g_kv);
    cudaGetSymbolAddress((void**)&sc, g_sc);

    cudaFuncSetAttribute(tgemm<0>, cudaFuncAttributeMaxDynamicSharedMemorySize, SMEM_BYTES);
    cudaFuncSetAttribute(tgemm<1>, cudaFuncAttributeMaxDynamicSharedMemorySize, SMEM_BYTES);

    do_split(x,     x_hi,    x_lo,    XN);
    do_split(q_w,   qw_hi,   qw_lo,   (long long)EMBED * EMBED);
    do_split(kvd_w, kvdw_hi, kvdw_lo, (long long)LATENT * EMBED);
    do_split(kvu_w, kvuw_hi, kvuw_lo, (long long)2 * EMBED * LATENT);
    do_split(out_w, ow_hi,   ow_lo,   (long long)EMBED * EMBED);

    const int M = BSZ * SEQ;  // 4096

    // 1) q = x @ q_w^T + q_b   -> hi/lo planes
    tgemm<1><<<dim3(EMBED / 128, M / 128, 1), 256, SMEM_BYTES>>>(
        x_hi, x_lo, EMBED, qw_hi, qw_lo, EMBED, q_b, 1.f,
        nullptr, q_hi, q_lo, EMBED, EMBED, 1, 0, 0, 0, 0, 0, 0);

    // 2) latent = x @ kvd_w^T + kvd_b -> hi/lo
    tgemm<1><<<dim3(LATENT / 128, M / 128, 1), 256, SMEM_BYTES>>>(
        x_hi, x_lo, EMBED, kvdw_hi, kvdw_lo, EMBED, kvd_b, 1.f,
        nullptr, lat_hi, lat_lo, LATENT, EMBED, 1, 0, 0, 0, 0, 0, 0);

    // 3) kv = latent @ kvu_w^T + kvu_b -> fp32
    tgemm<0><<<dim3(2 * EMBED / 128, M / 128, 1), 256, SMEM_BYTES>>>(
        lat_hi, lat_lo, LATENT, kvuw_hi, kvuw_lo, LATENT, kvu_b, 1.f,
        kv, nullptr, nullptr, 2 * EMBED, LATENT, 1, 0, 0, 0, 0, 0, 0);

    // 4) k split + v transpose-split
    ksplit_kernel<<<(unsigned)(XN / 4 / 256), 256>>>(kv, k_hi, k_lo);
    vtrans_kernel<<<dim3(SEQ / 32, HD / 32, BSZ * NH), dim3(32, 32)>>>(kv, vt_hi, vt_lo);

    // 5) scores = (q_h @ k_h^T)/sqrt(D) -> fp32, batched over (b,h)
    const long long sQb = (long long)SEQ * EMBED;
    const long long sSz = (long long)SEQ * SEQ;
    tgemm<0><<<dim3(SEQ / 128, SEQ / 128, BSZ * NH), 256, SMEM_BYTES>>>(
        q_hi, q_lo, EMBED, k_hi, k_lo, EMBED, nullptr, 1.f / sqrtf((float)HD),
        sc, nullptr, nullptr, SEQ, HD, NH,
        sQb, (long long)HD, sQb, (long long)HD, sSz * NH, sSz);

    // 6) softmax -> P hi/lo
    softmax_split<<<BSZ * NH * SEQ, 256>>>(sc, p_hi, p_lo, SEQ);

    // 7) att = P @ vt^T -> hi/lo planes, batched over (b,h)
    tgemm<1><<<dim3(HD / 128, SEQ / 128, BSZ * NH), 256, SMEM_BYTES>>>(
        p_hi, p_lo, SEQ, vt_hi, vt_lo, SEQ, nullptr, 1.f,
        nullptr, att_hi, att_lo, EMBED, SEQ, NH,
        sSz * NH, sSz, (long long)NH * HD * SEQ, (long long)HD * SEQ,
        sQb, (long long)HD);

    // 8) out = att @ out_w^T + out_b -> fp32 (d_out)
    tgemm<0><<<dim3(EMBED / 128, M / 128, 1), 256, SMEM_BYTES>>>(
        att_hi, att_lo, EMBED, ow_hi, ow_lo, EMBED, out_b, 1.f,
        out, nullptr, nullptr, EMBED, EMBED, 1, 0, 0, 0, 0, 0, 0);
}